// round 17
// baseline (speedup 1.0000x reference)
#include <cuda_runtime.h>

// FMREDynamicDropout: out = x * bernoulli_mask(threefry2x32, keep_prob[c])
// x: [32, 384, 56, 56] fp32, feature_importance: [384] fp32
//
// JAX (threefry_partitionable) semantics, verified bit-exact since R2:
//   key(42) -> (0, 42); ks2 = 0 ^ 42 ^ 0x1BD11BDA = 0x1BD11BF0
//   per element i: hash counter words (0, i); bits[i] = o0 ^ o1
//   mask = bits < (ceil(keep[c] * 2^23) << 9)   (pure uint compare)
//
// R16: single launch, ZERO barriers in the hot path. Fused designs with a
// per-CTA barrier all cost ~+7us (R13/R14/R15: early bar, late bar — same)
// => the intra-block rendezvous itself is the tax. Here block 0 alone
// computes all 384 thresholds (256-thread-parallel, ~0.4us) and publishes
// them with a release-store flag; every other block spin-reads the flag
// (acquire) and loads its threshold via __ldcg (L2, no stale-L1 issue),
// both issued BEFORE the hash so the latency hides under ~1500cyc of
// integer work. Hash/select body is VERBATIM R8 (95.4us kernel, the
// measured alu-pipe floor). Determinism across graph replays: the
// last-exiting block (atomic counter) resets flag+counter, so every
// launch starts from flag=0 and does identical work.

#define NCH   384
#define HW    3136u
#define NTOT  38535168u   // 32*384*56*56
#define KS2   0x1BD11BF0u
#define GRID  18816u

__device__ unsigned g_thresh[NCH];   // pre-shifted: ceil(keep*2^23) << 9
__device__ unsigned g_flag = 0u;     // 1 = thresholds published (reset at end)
__device__ unsigned g_done = 0u;     // exit counter for the reset

// threefry round: add as x1*ONE+x0 (ONE runtime param; ptxas balances
// IMAD<->IADD3), funnel-shift + xor on alu. Bit-exact since R2.
#define TFR(rot) do { x0 = x1 * ONE + x0;                              \
                      x1 = __funnelshift_l(x1, x1, (rot)) ^ x0; } while (0)

// returns o0 ^ o1 for counter words (0, i), key (0, 42)   [verbatim R8]
__device__ __forceinline__ unsigned tf_bits(unsigned i, unsigned ONE) {
    unsigned x1 = i * ONE + 42u;            // counter + ks1
    unsigned x0 = x1;                       // round-1 add: 0 + x1  (copy)
    x1 = __funnelshift_l(x1, x1, 13) ^ x0;  // round 1  (rot 13)
    TFR(15); TFR(26); TFR(6);               // rounds 2-4
    x0 = x0 * ONE + 42u;                    // inject: x0 += ks1
    x1 = x1 * ONE + (KS2 + 1u);             //         x1 += ks2 + 1
    TFR(17); TFR(29); TFR(16); TFR(24);     // rounds 5-8
    x0 = x0 * ONE + KS2;                    // inject: x0 += ks2
    x1 = x1 * ONE + 2u;                     //         x1 += ks0 + 2
    TFR(13); TFR(15); TFR(26); TFR(6);      // rounds 9-12
    x1 = x1 * ONE + 45u;                    // inject: x1 += ks1+3 (x0 += 0)
    TFR(17); TFR(29); TFR(16); TFR(24);     // rounds 13-16
    x0 = x0 * ONE + 42u;                    // inject: x0 += ks1
    x1 = x1 * ONE + (KS2 + 4u);             //         x1 += ks2 + 4
    TFR(13); TFR(15); TFR(26); TFR(6);      // rounds 17-20
    x0 = x0 * ONE + KS2;                    // final inject x0 += ks2
    x1 = x1 * ONE + 5u;                     //              x1 += ks0 + 5
    return x0 ^ x1;                         // output xor
}

// threshold for one channel value, byte-identical fp sequence to reference
__device__ __forceinline__ unsigned chan_thresh(float v, float fmin, float fmax) {
    float scaled = __fdiv_rn(__fsub_rn(v, fmin), __fsub_rn(fmax, fmin));
    float rate   = __fadd_rn(0.1f, __fmul_rn(0.4f, __fsub_rn(1.0f, scaled)));
    float keep   = __fsub_rn(1.0f, rate);
    return ((unsigned)ceilf(__fmul_rn(keep, 8388608.0f))) << 9;   // <= 0.9*2^23
}

// ---------------- fused kernel: block0 publishes, others spin-read ----------
__global__ void __launch_bounds__(256, 8)
drop_kernel(const float* __restrict__ x, const float* __restrict__ fi,
            float* __restrict__ out, unsigned ONE) {
    int tid = threadIdx.x;
    unsigned bid = blockIdx.x;
    unsigned j = (bid * 256u + tid) * 8u;      // j < NTOT, 8 | HW
    unsigned c = (j / HW) % (unsigned)NCH;     // channel (8 elems share it)

    // issue x loads first (DRAM latency hides under prep/spin/hash)
    float4 a = *reinterpret_cast<const float4*>(x + j);
    float4 b = *reinterpret_cast<const float4*>(x + j + 4);

    unsigned T;
    if (bid == 0) {
        // ---- 256-thread-parallel prep: min/max + all 384 thresholds --------
        __shared__ float smn[8], smx[8];
        __shared__ unsigned sT0;
        float v0 = fi[tid];
        float v1 = (tid < 128) ? fi[tid + 256] : v0;
        float mn = fminf(v0, v1), mx = fmaxf(v0, v1);
        #pragma unroll
        for (int o = 16; o > 0; o >>= 1) {
            mn = fminf(mn, __shfl_xor_sync(0xffffffffu, mn, o));
            mx = fmaxf(mx, __shfl_xor_sync(0xffffffffu, mx, o));
        }
        if ((tid & 31) == 0) { smn[tid >> 5] = mn; smx[tid >> 5] = mx; }
        __syncthreads();
        float fmin = smn[0], fmax = smx[0];
        #pragma unroll
        for (int i = 1; i < 8; i++) {
            fmin = fminf(fmin, smn[i]);
            fmax = fmaxf(fmax, smx[i]);
        }
        unsigned t0 = chan_thresh(v0, fmin, fmax);      // channel tid
        g_thresh[tid] = t0;
        if (tid < 128)                                   // channels 256..383
            g_thresh[tid + 256] = chan_thresh(v1, fmin, fmax);
        if (tid == 0) sT0 = t0;                          // block0 is channel 0
        __threadfence();            // make this thread's STGs gpu-visible
        __syncthreads();            // all threads' fenced stores done
        if (tid == 0)
            asm volatile("st.release.gpu.global.u32 [%0], %1;"
                         :: "l"(&g_flag), "r"(1u) : "memory");
        T = sT0;                    // block0 spans only channel 0 (2048 < HW)
    } else {
        // ---- spin on publish flag (1 iteration after wave 1), then T -------
        unsigned f;
        do {
            asm volatile("ld.acquire.gpu.global.u32 %0, [%1];"
                         : "=r"(f) : "l"(&g_flag) : "memory");
        } while (f == 0u);
        T = __ldcg(&g_thresh[c]);   // L2 read; latency hides under the hash
    }

    // ---- hash + select (verbatim R8 body) ----------------------------------
    unsigned m[8];
    #pragma unroll
    for (int k = 0; k < 8; k++)
        m[k] = tf_bits(j + (unsigned)k, ONE);

    float4 oa, ob;
    oa.x = (m[0] < T) ? a.x : 0.0f;
    oa.y = (m[1] < T) ? a.y : 0.0f;
    oa.z = (m[2] < T) ? a.z : 0.0f;
    oa.w = (m[3] < T) ? a.w : 0.0f;
    ob.x = (m[4] < T) ? b.x : 0.0f;
    ob.y = (m[5] < T) ? b.y : 0.0f;
    ob.z = (m[6] < T) ? b.z : 0.0f;
    ob.w = (m[7] < T) ? b.w : 0.0f;

    *reinterpret_cast<float4*>(out + j)     = oa;
    *reinterpret_cast<float4*>(out + j + 4) = ob;

    // ---- deterministic reset: last block to exit clears flag + counter -----
    if (tid == 0) {
        unsigned old = atomicAdd(&g_done, 1u);
        if (old == GRID - 1u) {          // all blocks are past their spin
            atomicExch(&g_done, 0u);
            atomicExch(&g_flag, 0u);     // next launch starts identically
        }
    }
}

extern "C" void kernel_launch(void* const* d_in, const int* in_sizes, int n_in,
                              void* d_out, int out_size) {
    const float* x  = (const float*)d_in[0];
    const float* fi = (const float*)d_in[1];
    if (n_in >= 2 && in_sizes[0] == NCH) {   // robust to input ordering
        x  = (const float*)d_in[1];
        fi = (const float*)d_in[0];
    }
    // single launch; ONE = 1 at runtime (opaque add-steering hint)
    // NTOT / 8 elems-per-thread / 256 threads = 18816 blocks, no remainder
    drop_kernel<<<GRID, 256>>>(x, fi, (float*)d_out, 1u);
}